// round 3
// baseline (speedup 1.0000x reference)
#include <cuda_runtime.h>
#include <math.h>

#define NB 16
#define NC 256
#define NNP 2304   // N = 48*48 pixels
#define ND 32      // d = C/8
#define NR 320     // packed qkv rows: 32 q + 32 k + 256 v

// ---- scratch (static device globals; no allocation at runtime) ----
__device__ float g_W[NR * NC];                       // packed weights
__device__ float g_bias[NR];                         // packed biases
__device__ float g_qkv[(size_t)NB * NR * NNP];       // 47 MB
__device__ float g_energy[(size_t)NB * NNP * NNP];   // 340 MB, stored E^T[j][i]
__device__ float g_L[NB * NNP];                      // M[j] + log S[j]

// ---------------------------------------------------------------------------
// K0: pack Wq/Wk/Wv and biases into one [320 x 256] matrix
// ---------------------------------------------------------------------------
__global__ void pack_w_kernel(const float* __restrict__ Wq, const float* __restrict__ bq,
                              const float* __restrict__ Wk, const float* __restrict__ bk,
                              const float* __restrict__ Wv, const float* __restrict__ bv) {
    int idx = blockIdx.x * blockDim.x + threadIdx.x;
    if (idx < NR * NC) {
        int r = idx / NC, c = idx - r * NC;
        float v;
        if (r < ND)          v = Wq[r * NC + c];
        else if (r < 2 * ND) v = Wk[(r - ND) * NC + c];
        else                 v = Wv[(r - 2 * ND) * NC + c];
        g_W[idx] = v;
    }
    if (idx < NR) {
        float v;
        if (idx < ND)          v = bq[idx];
        else if (idx < 2 * ND) v = bk[idx - ND];
        else                   v = bv[idx - 2 * ND];
        g_bias[idx] = v;
    }
}

// ---------------------------------------------------------------------------
// K1: qkv[b][r][n] = sum_c W[r][c] * x[b][c][n] + bias[r]
// NN GEMM, 64x64x16 tiles, 4x4 microtile
// ---------------------------------------------------------------------------
__global__ __launch_bounds__(256) void qkv_gemm_kernel(const float* __restrict__ x) {
    int b = blockIdx.z;
    int m0 = blockIdx.y * 64;
    int n0 = blockIdx.x * 64;
    const float* A  = g_W;                             // [NR, NC] row-major
    const float* Bm = x + (size_t)b * NC * NNP;        // [NC, NNP] row-major
    float* Cm = g_qkv + (size_t)b * NR * NNP;

    __shared__ float As[16][64];
    __shared__ float Bs[16][64];
    int tid = threadIdx.x;
    int tx = tid & 15, ty = tid >> 4;
    float acc[4][4] = {};

    for (int k0 = 0; k0 < NC; k0 += 16) {
        int ar = tid >> 2, ac = (tid & 3) * 4;
        float4 av = *(const float4*)(A + (size_t)(m0 + ar) * NC + k0 + ac);
        As[ac + 0][ar] = av.x; As[ac + 1][ar] = av.y;
        As[ac + 2][ar] = av.z; As[ac + 3][ar] = av.w;
        int br = tid >> 4, bc = (tid & 15) * 4;
        *(float4*)&Bs[br][bc] = *(const float4*)(Bm + (size_t)(k0 + br) * NNP + n0 + bc);
        __syncthreads();
#pragma unroll
        for (int kk = 0; kk < 16; kk++) {
            float a[4], bb[4];
            *(float4*)a  = *(const float4*)&As[kk][ty * 4];
            *(float4*)bb = *(const float4*)&Bs[kk][tx * 4];
#pragma unroll
            for (int i = 0; i < 4; i++)
#pragma unroll
                for (int j = 0; j < 4; j++)
                    acc[i][j] += a[i] * bb[j];
        }
        __syncthreads();
    }
#pragma unroll
    for (int i = 0; i < 4; i++) {
        int m = m0 + ty * 4 + i;
        float bias = g_bias[m];
        float4 o;
        o.x = acc[i][0] + bias; o.y = acc[i][1] + bias;
        o.z = acc[i][2] + bias; o.w = acc[i][3] + bias;
        *(float4*)(Cm + (size_t)m * NNP + n0 + tx * 4) = o;
    }
}

// ---------------------------------------------------------------------------
// K2: E^T[b][j][i] = sum_d k[b][d][j] * q[b][d][i]
// TN GEMM (both operands K-major), 128x128x8 tiles, 8x8 split microtile
// ---------------------------------------------------------------------------
__global__ __launch_bounds__(256) void energy_gemm_kernel() {
    int b = blockIdx.z;
    int j0 = blockIdx.y * 128;
    int i0 = blockIdx.x * 128;
    const float* A  = g_qkv + (size_t)b * NR * NNP + (size_t)ND * NNP;  // k: [32][NNP]
    const float* Bq = g_qkv + (size_t)b * NR * NNP;                     // q: [32][NNP]
    float* Cm = g_energy + (size_t)b * NNP * NNP;

    __shared__ float As[8][128];
    __shared__ float Bs[8][128];
    int tid = threadIdx.x;
    int tx = tid & 15, ty = tid >> 4;
    float acc[8][8] = {};

    for (int k0 = 0; k0 < ND; k0 += 8) {
        int lr = tid >> 5, lc = (tid & 31) * 4;
        *(float4*)&As[lr][lc] = *(const float4*)(A  + (size_t)(k0 + lr) * NNP + j0 + lc);
        *(float4*)&Bs[lr][lc] = *(const float4*)(Bq + (size_t)(k0 + lr) * NNP + i0 + lc);
        __syncthreads();
#pragma unroll
        for (int kk = 0; kk < 8; kk++) {
            float a[8], bb[8];
            *(float4*)&a[0]  = *(const float4*)&As[kk][ty * 4];
            *(float4*)&a[4]  = *(const float4*)&As[kk][64 + ty * 4];
            *(float4*)&bb[0] = *(const float4*)&Bs[kk][tx * 4];
            *(float4*)&bb[4] = *(const float4*)&Bs[kk][64 + tx * 4];
#pragma unroll
            for (int i = 0; i < 8; i++)
#pragma unroll
                for (int j = 0; j < 8; j++)
                    acc[i][j] += a[i] * bb[j];
        }
        __syncthreads();
    }
#pragma unroll
    for (int ih = 0; ih < 2; ih++)
#pragma unroll
        for (int i = 0; i < 4; i++) {
            int j = j0 + ih * 64 + ty * 4 + i;
#pragma unroll
            for (int jh = 0; jh < 2; jh++) {
                float4 o;
                o.x = acc[ih * 4 + i][jh * 4 + 0];
                o.y = acc[ih * 4 + i][jh * 4 + 1];
                o.z = acc[ih * 4 + i][jh * 4 + 2];
                o.w = acc[ih * 4 + i][jh * 4 + 3];
                *(float4*)(Cm + (size_t)j * NNP + i0 + jh * 64 + tx * 4) = o;
            }
        }
}

// ---------------------------------------------------------------------------
// K3: per key-column j (= contiguous row of E^T): L[j] = max_i + log(sum_i exp)
// ---------------------------------------------------------------------------
__global__ __launch_bounds__(256) void softmax_stats_kernel() {
    int b = blockIdx.y;
    int j = blockIdx.x;
    const float* row = g_energy + (size_t)b * NNP * NNP + (size_t)j * NNP;
    int tid = threadIdx.x;

    float vals[9];   // 2304 = 9 * 256
    float m = -1e30f;
#pragma unroll
    for (int u = 0; u < 9; u++) {
        vals[u] = row[tid + u * 256];
        m = fmaxf(m, vals[u]);
    }
    __shared__ float red[256];
    red[tid] = m; __syncthreads();
    for (int s = 128; s > 0; s >>= 1) {
        if (tid < s) red[tid] = fmaxf(red[tid], red[tid + s]);
        __syncthreads();
    }
    m = red[0]; __syncthreads();
    float sum = 0.f;
#pragma unroll
    for (int u = 0; u < 9; u++) sum += __expf(vals[u] - m);
    red[tid] = sum; __syncthreads();
    for (int s = 128; s > 0; s >>= 1) {
        if (tid < s) red[tid] += red[tid + s];
        __syncthreads();
    }
    if (tid == 0) g_L[b * NNP + j] = m + __logf(red[0]);
}

// ---------------------------------------------------------------------------
// K4: out[b][c][i] = gamma * sum_j v[b][c][j] * exp(E^T[j][i] - L[j]) + x[b][c][i]
// NN GEMM, exp fused into B-tile load, residual+gamma fused into epilogue
// ---------------------------------------------------------------------------
__global__ __launch_bounds__(256) void out_gemm_kernel(const float* __restrict__ x,
                                                       const float* __restrict__ gamma,
                                                       float* __restrict__ out) {
    int b = blockIdx.z;
    int m0 = blockIdx.y * 128;  // channel c
    int n0 = blockIdx.x * 128;  // pixel i
    const float* A  = g_qkv + (size_t)b * NR * NNP + (size_t)(2 * ND) * NNP; // v [256][NNP]
    const float* Bm = g_energy + (size_t)b * NNP * NNP;                      // E^T [j][i]
    const float* Lr = g_L + b * NNP;

    __shared__ float As[8][128];
    __shared__ float Bs[8][128];
    int tid = threadIdx.x;
    int tx = tid & 15, ty = tid >> 4;
    float acc[8][8] = {};

    for (int k0 = 0; k0 < NNP; k0 += 8) {
        int ar = tid >> 1, ac = (tid & 1) * 4;
        float4 av = *(const float4*)(A + (size_t)(m0 + ar) * NNP + k0 + ac);
        As[ac + 0][ar] = av.x; As[ac + 1][ar] = av.y;
        As[ac + 2][ar] = av.z; As[ac + 3][ar] = av.w;

        int brr = tid >> 5, bc = (tid & 31) * 4;
        float Lk = Lr[k0 + brr];
        float4 e = *(const float4*)(Bm + (size_t)(k0 + brr) * NNP + n0 + bc);
        e.x = __expf(e.x - Lk); e.y = __expf(e.y - Lk);
        e.z = __expf(e.z - Lk); e.w = __expf(e.w - Lk);
        *(float4*)&Bs[brr][bc] = e;
        __syncthreads();
#pragma unroll
        for (int kk = 0; kk < 8; kk++) {
            float a[8], bb[8];
            *(float4*)&a[0]  = *(const float4*)&As[kk][ty * 4];
            *(float4*)&a[4]  = *(const float4*)&As[kk][64 + ty * 4];
            *(float4*)&bb[0] = *(const float4*)&Bs[kk][tx * 4];
            *(float4*)&bb[4] = *(const float4*)&Bs[kk][64 + tx * 4];
#pragma unroll
            for (int i = 0; i < 8; i++)
#pragma unroll
                for (int j = 0; j < 8; j++)
                    acc[i][j] += a[i] * bb[j];
        }
        __syncthreads();
    }
    float g = gamma[0];
#pragma unroll
    for (int ih = 0; ih < 2; ih++)
#pragma unroll
        for (int i = 0; i < 4; i++) {
            int c = m0 + ih * 64 + ty * 4 + i;
            const float* xr = x + (size_t)b * NC * NNP + (size_t)c * NNP;
            float* orow = out + (size_t)b * NC * NNP + (size_t)c * NNP;
#pragma unroll
            for (int jh = 0; jh < 2; jh++) {
                int n = n0 + jh * 64 + tx * 4;
                float4 xv = *(const float4*)(xr + n);
                float4 o;
                o.x = g * acc[ih * 4 + i][jh * 4 + 0] + xv.x;
                o.y = g * acc[ih * 4 + i][jh * 4 + 1] + xv.y;
                o.z = g * acc[ih * 4 + i][jh * 4 + 2] + xv.z;
                o.w = g * acc[ih * 4 + i][jh * 4 + 3] + xv.w;
                *(float4*)(orow + n) = o;
            }
        }
}

// ---------------------------------------------------------------------------
extern "C" void kernel_launch(void* const* d_in, const int* in_sizes, int n_in,
                              void* d_out, int out_size) {
    const float* x     = (const float*)d_in[0];
    const float* Wq    = (const float*)d_in[1];
    const float* bq    = (const float*)d_in[2];
    const float* Wk    = (const float*)d_in[3];
    const float* bk    = (const float*)d_in[4];
    const float* Wv    = (const float*)d_in[5];
    const float* bv    = (const float*)d_in[6];
    const float* gamma = (const float*)d_in[7];
    float* out = (float*)d_out;

    pack_w_kernel<<<(NR * NC + 255) / 256, 256>>>(Wq, bq, Wk, bk, Wv, bv);

    dim3 g1(NNP / 64, NR / 64, NB);       // 36 x 5 x 16
    qkv_gemm_kernel<<<g1, 256>>>(x);

    dim3 g2(NNP / 128, NNP / 128, NB);    // 18 x 18 x 16
    energy_gemm_kernel<<<g2, 256>>>();

    dim3 g3(NNP, NB);                     // 2304 x 16
    softmax_stats_kernel<<<g3, 256>>>();

    dim3 g4(NNP / 128, NC / 128, NB);     // 18 x 2 x 16
    out_gemm_kernel<<<g4, 256>>>(x, gamma, out);
}

// round 6
// speedup vs baseline: 1.1545x; 1.1545x over previous
#include <cuda_runtime.h>
#include <math.h>
#include <cstdint>

#define NB 16
#define NC 256
#define NNP 2304   // N = 48*48 pixels
#define ND 32      // d = C/8
#define NR 320     // packed qkv rows: 32 q + 32 k + 256 v

// ---- scratch (static device globals; no allocation at runtime) ----
__device__ float g_W[NR * NC];
__device__ float g_bias[NR];
__device__ float g_qkv[(size_t)NB * NR * NNP];       // 47 MB
__device__ float g_energy[(size_t)NB * NNP * NNP];   // 340 MB, stored E^T[j][i]
__device__ float g_L[NB * NNP];                      // M[j] + log S[j]

__device__ __forceinline__ uint32_t f2tf32(float f) {
    uint32_t r; asm("cvt.rna.tf32.f32 %0, %1;" : "=r"(r) : "f"(f)); return r;
}
__device__ __forceinline__ void mma_tf32(float* c, const uint32_t* a, const uint32_t* b) {
    asm volatile(
        "mma.sync.aligned.m16n8k8.row.col.f32.tf32.tf32.f32 "
        "{%0,%1,%2,%3}, {%4,%5,%6,%7}, {%8,%9}, {%0,%1,%2,%3};"
        : "+f"(c[0]), "+f"(c[1]), "+f"(c[2]), "+f"(c[3])
        : "r"(a[0]), "r"(a[1]), "r"(a[2]), "r"(a[3]), "r"(b[0]), "r"(b[1]));
}

// ---------------------------------------------------------------------------
// K0: pack weights + biases
// ---------------------------------------------------------------------------
__global__ void pack_w_kernel(const float* __restrict__ Wq, const float* __restrict__ bq,
                              const float* __restrict__ Wk, const float* __restrict__ bk,
                              const float* __restrict__ Wv, const float* __restrict__ bv) {
    int idx = blockIdx.x * blockDim.x + threadIdx.x;
    if (idx < NR * NC) {
        int r = idx / NC, c = idx - r * NC;
        float v;
        if (r < ND)          v = Wq[r * NC + c];
        else if (r < 2 * ND) v = Wk[(r - ND) * NC + c];
        else                 v = Wv[(r - 2 * ND) * NC + c];
        g_W[idx] = v;
    }
    if (idx < NR) {
        float v;
        if (idx < ND)          v = bq[idx];
        else if (idx < 2 * ND) v = bk[idx - ND];
        else                   v = bv[idx - 2 * ND];
        g_bias[idx] = v;
    }
}

// ---------------------------------------------------------------------------
// K1: qkv projection GEMM (fp32 SIMT)
// ---------------------------------------------------------------------------
__global__ __launch_bounds__(256) void qkv_gemm_kernel(const float* __restrict__ x) {
    int b = blockIdx.z;
    int m0 = blockIdx.y * 64;
    int n0 = blockIdx.x * 64;
    const float* A  = g_W;
    const float* Bm = x + (size_t)b * NC * NNP;
    float* Cm = g_qkv + (size_t)b * NR * NNP;

    __shared__ float As[16][64];
    __shared__ float Bs[16][64];
    int tid = threadIdx.x;
    int tx = tid & 15, ty = tid >> 4;
    float acc[4][4] = {};

    for (int k0 = 0; k0 < NC; k0 += 16) {
        int ar = tid >> 2, ac = (tid & 3) * 4;
        float4 av = *(const float4*)(A + (size_t)(m0 + ar) * NC + k0 + ac);
        As[ac + 0][ar] = av.x; As[ac + 1][ar] = av.y;
        As[ac + 2][ar] = av.z; As[ac + 3][ar] = av.w;
        int br = tid >> 4, bc = (tid & 15) * 4;
        *(float4*)&Bs[br][bc] = *(const float4*)(Bm + (size_t)(k0 + br) * NNP + n0 + bc);
        __syncthreads();
#pragma unroll
        for (int kk = 0; kk < 16; kk++) {
            float a[4], bb[4];
            *(float4*)a  = *(const float4*)&As[kk][ty * 4];
            *(float4*)bb = *(const float4*)&Bs[kk][tx * 4];
#pragma unroll
            for (int i = 0; i < 4; i++)
#pragma unroll
                for (int j = 0; j < 4; j++)
                    acc[i][j] += a[i] * bb[j];
        }
        __syncthreads();
    }
#pragma unroll
    for (int i = 0; i < 4; i++) {
        int m = m0 + ty * 4 + i;
        float bias = g_bias[m];
        float4 o;
        o.x = acc[i][0] + bias; o.y = acc[i][1] + bias;
        o.z = acc[i][2] + bias; o.w = acc[i][3] + bias;
        *(float4*)(Cm + (size_t)m * NNP + n0 + tx * 4) = o;
    }
}

// ---------------------------------------------------------------------------
// K2: E^T[b][j][i] = k . q  (fp32 SIMT, exact for softmax)
// ---------------------------------------------------------------------------
__global__ __launch_bounds__(256) void energy_gemm_kernel() {
    int b = blockIdx.z;
    int j0 = blockIdx.y * 128;
    int i0 = blockIdx.x * 128;
    const float* A  = g_qkv + (size_t)b * NR * NNP + (size_t)ND * NNP;
    const float* Bq = g_qkv + (size_t)b * NR * NNP;
    float* Cm = g_energy + (size_t)b * NNP * NNP;

    __shared__ float As[8][128];
    __shared__ float Bs[8][128];
    int tid = threadIdx.x;
    int tx = tid & 15, ty = tid >> 4;
    float acc[8][8] = {};

    for (int k0 = 0; k0 < ND; k0 += 8) {
        int lr = tid >> 5, lc = (tid & 31) * 4;
        *(float4*)&As[lr][lc] = *(const float4*)(A  + (size_t)(k0 + lr) * NNP + j0 + lc);
        *(float4*)&Bs[lr][lc] = *(const float4*)(Bq + (size_t)(k0 + lr) * NNP + i0 + lc);
        __syncthreads();
#pragma unroll
        for (int kk = 0; kk < 8; kk++) {
            float a[8], bb[8];
            *(float4*)&a[0]  = *(const float4*)&As[kk][ty * 4];
            *(float4*)&a[4]  = *(const float4*)&As[kk][64 + ty * 4];
            *(float4*)&bb[0] = *(const float4*)&Bs[kk][tx * 4];
            *(float4*)&bb[4] = *(const float4*)&Bs[kk][64 + tx * 4];
#pragma unroll
            for (int i = 0; i < 8; i++)
#pragma unroll
                for (int j = 0; j < 8; j++)
                    acc[i][j] += a[i] * bb[j];
        }
        __syncthreads();
    }
#pragma unroll
    for (int ih = 0; ih < 2; ih++)
#pragma unroll
        for (int i = 0; i < 4; i++) {
            int j = j0 + ih * 64 + ty * 4 + i;
#pragma unroll
            for (int jh = 0; jh < 2; jh++) {
                float4 o;
                o.x = acc[ih * 4 + i][jh * 4 + 0];
                o.y = acc[ih * 4 + i][jh * 4 + 1];
                o.z = acc[ih * 4 + i][jh * 4 + 2];
                o.w = acc[ih * 4 + i][jh * 4 + 3];
                *(float4*)(Cm + (size_t)j * NNP + i0 + jh * 64 + tx * 4) = o;
            }
        }
}

// ---------------------------------------------------------------------------
// K3: per-key-column stats  L[j] = max_i + log(sum_i exp)
// ---------------------------------------------------------------------------
__global__ __launch_bounds__(256) void softmax_stats_kernel() {
    int b = blockIdx.y;
    int j = blockIdx.x;
    const float* row = g_energy + (size_t)b * NNP * NNP + (size_t)j * NNP;
    int tid = threadIdx.x;

    float vals[9];
    float m = -1e30f;
#pragma unroll
    for (int u = 0; u < 9; u++) {
        vals[u] = row[tid + u * 256];
        m = fmaxf(m, vals[u]);
    }
    __shared__ float red[256];
    red[tid] = m; __syncthreads();
    for (int s = 128; s > 0; s >>= 1) {
        if (tid < s) red[tid] = fmaxf(red[tid], red[tid + s]);
        __syncthreads();
    }
    m = red[0]; __syncthreads();
    float sum = 0.f;
#pragma unroll
    for (int u = 0; u < 9; u++) sum += __expf(vals[u] - m);
    red[tid] = sum; __syncthreads();
    for (int s = 128; s > 0; s >>= 1) {
        if (tid < s) red[tid] += red[tid + s];
        __syncthreads();
    }
    if (tid == 0) g_L[b * NNP + j] = m + __logf(red[0]);
}

// ---------------------------------------------------------------------------
// K4: out = gamma * (V @ softmax-attn) + x  via mma.sync tf32 (m16n8k8)
// CTA: M=128 channels x N=256 pixels, K chunks of 32, double-buffered smem.
// A/B staged directly in mma FRAGMENT order -> conflict-free LDS.128/LDS.64.
// ---------------------------------------------------------------------------
#define KC 32
#define NT 256
#define MT 128
#define ITERS (NNP / KC)            // 72
// per-buffer: A frags 128*32 floats (16KB) + B frags 256*32 floats (32KB)
#define SBUF  49152
#define S_TOTAL (2 * SBUF)          // 96 KB dynamic smem

// A fragment slot: tile mt (m16), kstep ks (k8), lane, reg r(0..3)
//   element (m,k): mt=m>>4, lane=(m&7)*4+(k&3), r=((m>>3)&1) + ((k>>2)&1)*2
// B fragment slot: tile nt (n8), ks, lane, reg r(0..1)
//   element (k,n): nt=n>>3, lane=(n&7)*4+(k&3), r=(k>>2)&1

__device__ __forceinline__ void stage_AB(const float* __restrict__ Av,
                                         const float* __restrict__ BmI,
                                         const float* __restrict__ Lr,
                                         int k0, float* sA, float* sB, int tid) {
#pragma unroll
    for (int u = 0; u < 4; u++) {                 // A: 128 x 32
        int lin = tid + u * 256;
        int m = lin >> 3, k4 = (lin & 7) * 4;
        float4 av = *(const float4*)(Av + (size_t)m * NNP + k0 + k4);
        int mt = m >> 4, mr = m & 15, ks = k4 >> 3;
        int base = ((mt * 4 + ks) * 32 + (mr & 7) * 4) * 4 + (mr >> 3) + ((k4 >> 2) & 1) * 2;
        sA[base +  0] = __uint_as_float(f2tf32(av.x));
        sA[base +  4] = __uint_as_float(f2tf32(av.y));
        sA[base +  8] = __uint_as_float(f2tf32(av.z));
        sA[base + 12] = __uint_as_float(f2tf32(av.w));
    }
#pragma unroll
    for (int u = 0; u < 8; u++) {                 // B: 32(k) x 256(n), exp fused
        int lin = tid + u * 256;
        int n0l = (lin & 63) * 4;
        int k = lin >> 6;
        float4 ev = *(const float4*)(BmI + (size_t)(k0 + k) * NNP + n0l);
        float L = Lr[k0 + k];
        int nt = n0l >> 3, ks = k >> 3;
        int base = ((nt * 4 + ks) * 32 + (n0l & 7) * 4 + (k & 3)) * 2 + ((k >> 2) & 1);
        sB[base +  0] = __uint_as_float(f2tf32(__expf(ev.x - L)));
        sB[base +  8] = __uint_as_float(f2tf32(__expf(ev.y - L)));
        sB[base + 16] = __uint_as_float(f2tf32(__expf(ev.z - L)));
        sB[base + 24] = __uint_as_float(f2tf32(__expf(ev.w - L)));
    }
}

__global__ __launch_bounds__(256, 1) void out_gemm_tc_kernel(const float* __restrict__ x,
                                                             const float* __restrict__ gamma,
                                                             float* __restrict__ out) {
    extern __shared__ float smem[];
    const int tid = threadIdx.x;
    const int lane = tid & 31;
    const int wid = tid >> 5;
    const int warp_m = wid & 1;        // 2 tiles of 64 rows
    const int warp_n = wid >> 1;       // 4 tiles of 64 cols

    const int b  = blockIdx.z;
    const int m0 = blockIdx.y * MT;    // channel base
    const int i0 = blockIdx.x * NT;    // pixel base

    const float* Av  = g_qkv + (size_t)b * NR * NNP + (size_t)(2 * ND + m0) * NNP;
    const float* BmI = g_energy + (size_t)b * NNP * NNP + i0;
    const float* Lr  = g_L + b * NNP;

    float acc[4][8][4];
#pragma unroll
    for (int i = 0; i < 4; i++)
#pragma unroll
        for (int j = 0; j < 8; j++)
#pragma unroll
            for (int r = 0; r < 4; r++) acc[i][j][r] = 0.f;

    stage_AB(Av, BmI, Lr, 0, smem, smem + 4096, tid);
    __syncthreads();

    for (int it = 0; it < ITERS; it++) {
        const int cur = it & 1;
        float* sAc = smem + cur * 12288;
        float* sBc = sAc + 4096;
        if (it + 1 < ITERS) {
            float* sAn = smem + (cur ^ 1) * 12288;
            stage_AB(Av, BmI, Lr, (it + 1) * KC, sAn, sAn + 4096, tid);
        }
        const uint32_t* uA = (const uint32_t*)sAc;
        const uint32_t* uB = (const uint32_t*)sBc;
#pragma unroll
        for (int ks = 0; ks < 4; ks++) {
            uint32_t a[4][4];
            uint32_t bfr[8][2];
#pragma unroll
            for (int i = 0; i < 4; i++) {
                int mt = warp_m * 4 + i;
                uint4 t = *(const uint4*)(uA + ((mt * 4 + ks) * 32 + lane) * 4);
                a[i][0] = t.x; a[i][1] = t.y; a[i][2] = t.z; a[i][3] = t.w;
            }
#pragma unroll
            for (int j = 0; j < 8; j++) {
                int nt = warp_n * 8 + j;
                uint2 t = *(const uint2*)(uB + ((nt * 4 + ks) * 32 + lane) * 2);
                bfr[j][0] = t.x; bfr[j][1] = t.y;
            }
#pragma unroll
            for (int i = 0; i < 4; i++)
#pragma unroll
                for (int j = 0; j < 8; j++)
                    mma_tf32(acc[i][j], a[i], bfr[j]);
        }
        __syncthreads();
    }

    // ---- epilogue: gamma*acc + x, float2 stores ----
    const float g = gamma[0];
    const float* xb = x + (size_t)b * NC * NNP;
    float* ob = out + (size_t)b * NC * NNP;
    const int gq = lane >> 2, tq = lane & 3;
#pragma unroll
    for (int i = 0; i < 4; i++) {
        int row0 = m0 + warp_m * 64 + i * 16 + gq;
#pragma unroll
        for (int j = 0; j < 8; j++) {
            int n = i0 + warp_n * 64 + j * 8 + tq * 2;
            size_t o0 = (size_t)row0 * NNP + n;
            size_t o1 = o0 + (size_t)8 * NNP;
            float2 x0 = *(const float2*)(xb + o0);
            float2 x1 = *(const float2*)(xb + o1);
            float2 r0, r1;
            r0.x = g * acc[i][j][0] + x0.x;
            r0.y = g * acc[i][j][1] + x0.y;
            r1.x = g * acc[i][j][2] + x1.x;
            r1.y = g * acc[i][j][3] + x1.y;
            *(float2*)(ob + o0) = r0;
            *(float2*)(ob + o1) = r1;
        }
    }
}

// ---------------------------------------------------------------------------
extern "C" void kernel_launch(void* const* d_in, const int* in_sizes, int n_in,
                              void* d_out, int out_size) {
    const float* x     = (const float*)d_in[0];
    const float* Wq    = (const float*)d_in[1];
    const float* bq    = (const float*)d_in[2];
    const float* Wk    = (const float*)d_in[3];
    const float* bk    = (const float*)d_in[4];
    const float* Wv    = (const float*)d_in[5];
    const float* bv    = (const float*)d_in[6];
    const float* gamma = (const float*)d_in[7];
    float* out = (float*)d_out;

    pack_w_kernel<<<(NR * NC + 255) / 256, 256>>>(Wq, bq, Wk, bk, Wv, bv);

    dim3 g1(NNP / 64, NR / 64, NB);
    qkv_gemm_kernel<<<g1, 256>>>(x);

    dim3 g2(NNP / 128, NNP / 128, NB);
    energy_gemm_kernel<<<g2, 256>>>();

    dim3 g3(NNP, NB);
    softmax_stats_kernel<<<g3, 256>>>();

    static bool attr_set = false;
    if (!attr_set) {
        cudaFuncSetAttribute(out_gemm_tc_kernel, cudaFuncAttributeMaxDynamicSharedMemorySize,
                             S_TOTAL * (int)sizeof(float) / (int)sizeof(float) == S_TOTAL ? S_TOTAL : S_TOTAL);
        attr_set = true;
    }
    cudaFuncSetAttribute(out_gemm_tc_kernel, cudaFuncAttributeMaxDynamicSharedMemorySize, S_TOTAL);
    dim3 g4(NNP / NT, NC / MT, NB);       // 9 x 2 x 16
    out_gemm_tc_kernel<<<g4, 256, S_TOTAL>>>(x, gamma, out);
}

// round 7
// speedup vs baseline: 1.6094x; 1.3940x over previous
#include <cuda_runtime.h>
#include <math.h>
#include <cstdint>

#define NB 16
#define NC 256
#define NNP 2304   // N = 48*48 pixels
#define ND 32      // d = C/8
#define NR 320     // packed qkv rows: 32 q + 32 k + 256 v
#define NKC 72     // k-chunks of 32 in NNP
#define NIT 18     // 128-pixel i-tiles in NNP

// ---- scratch (static device globals; no allocation at runtime) ----
__device__ float g_W[NR * NC];
__device__ float g_bias[NR];
__device__ float g_qkv[(size_t)NB * NR * NNP];         // 47 MB
__device__ float g_energy[(size_t)NB * NNP * NNP];     // 340 MB, E^T[j][i]
__device__ float g_L[NB * NNP];                        // M[j] + log S[j]
__device__ float g_P[(size_t)NB * NNP * NNP];          // 340 MB, fragment-ordered probs (tf32 bits)
__device__ float g_Vf[(size_t)NB * NKC * 8192];        // 38 MB, fragment-ordered v (tf32 bits)

__device__ __forceinline__ uint32_t f2tf32(float f) {
    uint32_t r; asm("cvt.rna.tf32.f32 %0, %1;" : "=r"(r) : "f"(f)); return r;
}
__device__ __forceinline__ void mma_tf32(float* c, const uint32_t* a, const uint32_t* b) {
    asm volatile(
        "mma.sync.aligned.m16n8k8.row.col.f32.tf32.tf32.f32 "
        "{%0,%1,%2,%3}, {%4,%5,%6,%7}, {%8,%9}, {%0,%1,%2,%3};"
        : "+f"(c[0]), "+f"(c[1]), "+f"(c[2]), "+f"(c[3])
        : "r"(a[0]), "r"(a[1]), "r"(a[2]), "r"(a[3]), "r"(b[0]), "r"(b[1]));
}
__device__ __forceinline__ void cp_async16(void* smem_dst, const void* gmem_src) {
    uint32_t sa = (uint32_t)__cvta_generic_to_shared(smem_dst);
    asm volatile("cp.async.cg.shared.global [%0], [%1], 16;" :: "r"(sa), "l"(gmem_src));
}
#define CP_COMMIT() asm volatile("cp.async.commit_group;" ::: "memory")
#define CP_WAIT(n)  asm volatile("cp.async.wait_group %0;" :: "n"(n) : "memory")

// ---------------------------------------------------------------------------
// K0: pack weights + biases
// ---------------------------------------------------------------------------
__global__ void pack_w_kernel(const float* __restrict__ Wq, const float* __restrict__ bq,
                              const float* __restrict__ Wk, const float* __restrict__ bk,
                              const float* __restrict__ Wv, const float* __restrict__ bv) {
    int idx = blockIdx.x * blockDim.x + threadIdx.x;
    if (idx < NR * NC) {
        int r = idx / NC, c = idx - r * NC;
        float v;
        if (r < ND)          v = Wq[r * NC + c];
        else if (r < 2 * ND) v = Wk[(r - ND) * NC + c];
        else                 v = Wv[(r - 2 * ND) * NC + c];
        g_W[idx] = v;
    }
    if (idx < NR) {
        float v;
        if (idx < ND)          v = bq[idx];
        else if (idx < 2 * ND) v = bk[idx - ND];
        else                   v = bv[idx - 2 * ND];
        g_bias[idx] = v;
    }
}

// ---------------------------------------------------------------------------
// K1: qkv projection GEMM (fp32 SIMT)
// ---------------------------------------------------------------------------
__global__ __launch_bounds__(256) void qkv_gemm_kernel(const float* __restrict__ x) {
    int b = blockIdx.z;
    int m0 = blockIdx.y * 64;
    int n0 = blockIdx.x * 64;
    const float* A  = g_W;
    const float* Bm = x + (size_t)b * NC * NNP;
    float* Cm = g_qkv + (size_t)b * NR * NNP;

    __shared__ float As[16][64];
    __shared__ float Bs[16][64];
    int tid = threadIdx.x;
    int tx = tid & 15, ty = tid >> 4;
    float acc[4][4] = {};

    for (int k0 = 0; k0 < NC; k0 += 16) {
        int ar = tid >> 2, ac = (tid & 3) * 4;
        float4 av = *(const float4*)(A + (size_t)(m0 + ar) * NC + k0 + ac);
        As[ac + 0][ar] = av.x; As[ac + 1][ar] = av.y;
        As[ac + 2][ar] = av.z; As[ac + 3][ar] = av.w;
        int br = tid >> 4, bc = (tid & 15) * 4;
        *(float4*)&Bs[br][bc] = *(const float4*)(Bm + (size_t)(k0 + br) * NNP + n0 + bc);
        __syncthreads();
#pragma unroll
        for (int kk = 0; kk < 16; kk++) {
            float a[4], bb[4];
            *(float4*)a  = *(const float4*)&As[kk][ty * 4];
            *(float4*)bb = *(const float4*)&Bs[kk][tx * 4];
#pragma unroll
            for (int i = 0; i < 4; i++)
#pragma unroll
                for (int j = 0; j < 4; j++)
                    acc[i][j] += a[i] * bb[j];
        }
        __syncthreads();
    }
#pragma unroll
    for (int i = 0; i < 4; i++) {
        int m = m0 + ty * 4 + i;
        float bias = g_bias[m];
        float4 o;
        o.x = acc[i][0] + bias; o.y = acc[i][1] + bias;
        o.z = acc[i][2] + bias; o.w = acc[i][3] + bias;
        *(float4*)(Cm + (size_t)m * NNP + n0 + tx * 4) = o;
    }
}

// ---------------------------------------------------------------------------
// K2: E^T[b][j][i] = k . q  (fp32 SIMT, exact for softmax)
// ---------------------------------------------------------------------------
__global__ __launch_bounds__(256) void energy_gemm_kernel() {
    int b = blockIdx.z;
    int j0 = blockIdx.y * 128;
    int i0 = blockIdx.x * 128;
    const float* A  = g_qkv + (size_t)b * NR * NNP + (size_t)ND * NNP;
    const float* Bq = g_qkv + (size_t)b * NR * NNP;
    float* Cm = g_energy + (size_t)b * NNP * NNP;

    __shared__ float As[8][128];
    __shared__ float Bs[8][128];
    int tid = threadIdx.x;
    int tx = tid & 15, ty = tid >> 4;
    float acc[8][8] = {};

    for (int k0 = 0; k0 < ND; k0 += 8) {
        int lr = tid >> 5, lc = (tid & 31) * 4;
        *(float4*)&As[lr][lc] = *(const float4*)(A  + (size_t)(k0 + lr) * NNP + j0 + lc);
        *(float4*)&Bs[lr][lc] = *(const float4*)(Bq + (size_t)(k0 + lr) * NNP + i0 + lc);
        __syncthreads();
#pragma unroll
        for (int kk = 0; kk < 8; kk++) {
            float a[8], bb[8];
            *(float4*)&a[0]  = *(const float4*)&As[kk][ty * 4];
            *(float4*)&a[4]  = *(const float4*)&As[kk][64 + ty * 4];
            *(float4*)&bb[0] = *(const float4*)&Bs[kk][tx * 4];
            *(float4*)&bb[4] = *(const float4*)&Bs[kk][64 + tx * 4];
#pragma unroll
            for (int i = 0; i < 8; i++)
#pragma unroll
                for (int j = 0; j < 8; j++)
                    acc[i][j] += a[i] * bb[j];
        }
        __syncthreads();
    }
#pragma unroll
    for (int ih = 0; ih < 2; ih++)
#pragma unroll
        for (int i = 0; i < 4; i++) {
            int j = j0 + ih * 64 + ty * 4 + i;
#pragma unroll
            for (int jh = 0; jh < 2; jh++) {
                float4 o;
                o.x = acc[ih * 4 + i][jh * 4 + 0];
                o.y = acc[ih * 4 + i][jh * 4 + 1];
                o.z = acc[ih * 4 + i][jh * 4 + 2];
                o.w = acc[ih * 4 + i][jh * 4 + 3];
                *(float4*)(Cm + (size_t)j * NNP + i0 + jh * 64 + tx * 4) = o;
            }
        }
}

// ---------------------------------------------------------------------------
// K3: per-key-column stats  L[j] = max_i + log(sum_i exp)
// ---------------------------------------------------------------------------
__global__ __launch_bounds__(256) void softmax_stats_kernel() {
    int b = blockIdx.y;
    int j = blockIdx.x;
    const float* row = g_energy + (size_t)b * NNP * NNP + (size_t)j * NNP;
    int tid = threadIdx.x;

    float vals[9];
    float m = -1e30f;
#pragma unroll
    for (int u = 0; u < 9; u++) {
        vals[u] = row[tid + u * 256];
        m = fmaxf(m, vals[u]);
    }
    __shared__ float red[256];
    red[tid] = m; __syncthreads();
    for (int s = 128; s > 0; s >>= 1) {
        if (tid < s) red[tid] = fmaxf(red[tid], red[tid + s]);
        __syncthreads();
    }
    m = red[0]; __syncthreads();
    float sum = 0.f;
#pragma unroll
    for (int u = 0; u < 9; u++) sum += __expf(vals[u] - m);
    red[tid] = sum; __syncthreads();
    for (int s = 128; s > 0; s >>= 1) {
        if (tid < s) red[tid] += red[tid + s];
        __syncthreads();
    }
    if (tid == 0) g_L[b * NNP + j] = m + __logf(red[0]);
}

// ---------------------------------------------------------------------------
// K3b: p_pack — P = exp(E^T - L) as tf32 bits, in mma B-fragment order.
// Tile (b, i-tile of 128, k-chunk of 32) -> contiguous 16KB block.
// slot(n,k) = ((nt*4+ks)*32 + (n&7)*4 + (k&3))*2 + ((k>>2)&1)
// Thread map: warp lanes span k&7 -> scatter is only 4-way conflicted.
// ---------------------------------------------------------------------------
__global__ __launch_bounds__(256) void p_pack_kernel() {
    int itile = blockIdx.x;         // 0..17
    int kc = blockIdx.y;            // 0..71
    int b  = blockIdx.z;
    const float* E = g_energy + (size_t)b * NNP * NNP + (size_t)(kc * 32) * NNP + itile * 128;
    const float* Lr = g_L + b * NNP + kc * 32;
    __shared__ float sp[4096];
    int t = threadIdx.x;
    int k  = ((t >> 6) << 3) | (t & 7);   // 0..31, lane spans k&7
    int fc = (t >> 3) & 7;                // float4-col group
    float L = Lr[k];
    const float* row = E + (size_t)k * NNP;
    int ks = k >> 3;
    int klow = (k & 3) * 2 + ((k >> 2) & 1);
#pragma unroll
    for (int u = 0; u < 4; u++) {
        int c4 = fc + u * 8;              // 0..31
        float4 e = *(const float4*)(row + c4 * 4);
        int n = c4 * 4;
        int b0 = ((n >> 3) * 4 + ks) * 64 + (n & 7) * 8 + klow;
        sp[b0 +  0] = __uint_as_float(f2tf32(__expf(e.x - L)));
        sp[b0 +  8] = __uint_as_float(f2tf32(__expf(e.y - L)));
        sp[b0 + 16] = __uint_as_float(f2tf32(__expf(e.z - L)));
        sp[b0 + 24] = __uint_as_float(f2tf32(__expf(e.w - L)));
    }
    __syncthreads();
    float4* dst = (float4*)(g_P + (((size_t)b * NIT + itile) * NKC + kc) * 4096);
    const float4* src = (const float4*)sp;
#pragma unroll
    for (int u = 0; u < 4; u++) dst[t + u * 256] = src[t + u * 256];
}

// ---------------------------------------------------------------------------
// K1b: vf_pack — v as tf32 bits in mma A-fragment order (MT=256 tile).
// slot(m,k) = 4*(((m>>4)*4+(k>>3))*32 + (m&7)*4 + (k&3)) + ((m>>3)&1) + 2*((k>>2)&1)
// ---------------------------------------------------------------------------
__global__ __launch_bounds__(256) void vf_pack_kernel() {
    int kc = blockIdx.x;     // 0..71
    int b  = blockIdx.y;
    const float* V = g_qkv + (size_t)b * NR * NNP + (size_t)(2 * ND) * NNP;
    __shared__ float sa[8192];
    int t = threadIdx.x;     // = channel row m
    const float* row = V + (size_t)t * NNP + kc * 32;
    int mt = t >> 4, mr = t & 15;
    int mpart = (mr & 7) * 4;
    int madd = (mr >> 3) & 1;
#pragma unroll
    for (int u = 0; u < 8; u++) {
        float4 v = *(const float4*)(row + u * 4);
        int ks = u >> 1;
        int base = ((mt * 4 + ks) * 32 + mpart) * 4 + madd + (u & 1) * 2;
        sa[base +  0] = __uint_as_float(f2tf32(v.x));
        sa[base +  4] = __uint_as_float(f2tf32(v.y));
        sa[base +  8] = __uint_as_float(f2tf32(v.z));
        sa[base + 12] = __uint_as_float(f2tf32(v.w));
    }
    __syncthreads();
    float4* dst = (float4*)(g_Vf + ((size_t)b * NKC + kc) * 8192);
    const float4* src = (const float4*)sa;
#pragma unroll
    for (int u = 0; u < 8; u++) dst[t + u * 256] = src[t + u * 256];
}

// ---------------------------------------------------------------------------
// K4: out = gamma * (V @ P) + x  via mma.sync tf32.
// CTA: M=256 (all channels) x N=128 pixels; K chunks of 32.
// Staging = pure cp.async 16B copies (prepacked fragments), double-buffered.
// ---------------------------------------------------------------------------
#define ITERS NKC
// per buffer: A 8192 floats (32KB) + B 4096 floats (16KB)
#define S_TOTAL (2 * 12288 * 4)     // 96 KB

__device__ __forceinline__ void og_prefetch(float* smem, const float* Vb, const float* Pb,
                                            int it2, int tid) {
    float* sA = smem + (it2 & 1) * 12288;
    float* sB = sA + 8192;
    const float4* srcA = (const float4*)(Vb + (size_t)it2 * 8192);
    const float4* srcB = (const float4*)(Pb + (size_t)it2 * 4096);
#pragma unroll
    for (int u = 0; u < 8; u++)
        cp_async16((float4*)sA + tid + u * 256, srcA + tid + u * 256);
#pragma unroll
    for (int u = 0; u < 4; u++)
        cp_async16((float4*)sB + tid + u * 256, srcB + tid + u * 256);
    CP_COMMIT();
}

__global__ __launch_bounds__(256, 1) void out_gemm_tc_kernel(const float* __restrict__ x,
                                                             const float* __restrict__ gamma,
                                                             float* __restrict__ out) {
    extern __shared__ float smem[];
    const int tid = threadIdx.x;
    const int lane = tid & 31;
    const int wid = tid >> 5;
    const int warp_m = wid & 3;        // 4 m-tiles of 64 rows
    const int warp_n = wid >> 2;       // 2 n-tiles of 64 cols

    const int itile = blockIdx.x;      // 0..17
    const int b = blockIdx.y;

    const float* Vb = g_Vf + (size_t)b * NKC * 8192;
    const float* Pb = g_P + (((size_t)b * NIT + itile) * NKC) * 4096;

    float acc[4][8][4];
#pragma unroll
    for (int i = 0; i < 4; i++)
#pragma unroll
        for (int j = 0; j < 8; j++)
#pragma unroll
            for (int r = 0; r < 4; r++) acc[i][j][r] = 0.f;

    og_prefetch(smem, Vb, Pb, 0, tid);
    og_prefetch(smem, Vb, Pb, 1, tid);

    for (int it = 0; it < ITERS; it++) {
        if (it < ITERS - 1) { CP_WAIT(1); } else { CP_WAIT(0); }
        __syncthreads();

        const uint32_t* uA = (const uint32_t*)(smem + (it & 1) * 12288);
        const uint32_t* uB = uA + 8192;
#pragma unroll
        for (int ks = 0; ks < 4; ks++) {
            uint32_t a[4][4];
            uint32_t bfr[8][2];
#pragma unroll
            for (int i = 0; i < 4; i++) {
                int mt = warp_m * 4 + i;
                uint4 tdat = *(const uint4*)(uA + ((mt * 4 + ks) * 32 + lane) * 4);
                a[i][0] = tdat.x; a[i][1] = tdat.y; a[i][2] = tdat.z; a[i][3] = tdat.w;
            }
#pragma unroll
            for (int j = 0; j < 8; j++) {
                int nt = warp_n * 8 + j;
                uint2 tdat = *(const uint2*)(uB + ((nt * 4 + ks) * 32 + lane) * 2);
                bfr[j][0] = tdat.x; bfr[j][1] = tdat.y;
            }
#pragma unroll
            for (int i = 0; i < 4; i++)
#pragma unroll
                for (int j = 0; j < 8; j++)
                    mma_tf32(acc[i][j], a[i], bfr[j]);
        }
        __syncthreads();
        if (it + 2 < ITERS) og_prefetch(smem, Vb, Pb, it + 2, tid);
    }

    // ---- epilogue: gamma*acc + x, float2 stores ----
    const float g = gamma[0];
    const float* xb = x + (size_t)b * NC * NNP;
    float* ob = out + (size_t)b * NC * NNP;
    const int gq = lane >> 2, tq = lane & 3;
#pragma unroll
    for (int i = 0; i < 4; i++) {
        int row0 = warp_m * 64 + i * 16 + gq;
#pragma unroll
        for (int j = 0; j < 8; j++) {
            int n = itile * 128 + warp_n * 64 + j * 8 + tq * 2;
            size_t o0 = (size_t)row0 * NNP + n;
            size_t o1 = o0 + (size_t)8 * NNP;
            float2 x0 = *(const float2*)(xb + o0);
            float2 x1 = *(const float2*)(xb + o1);
            float2 r0, r1;
            r0.x = g * acc[i][j][0] + x0.x;
            r0.y = g * acc[i][j][1] + x0.y;
            r1.x = g * acc[i][j][2] + x1.x;
            r1.y = g * acc[i][j][3] + x1.y;
            *(float2*)(ob + o0) = r0;
            *(float2*)(ob + o1) = r1;
        }
    }
}

// ---------------------------------------------------------------------------
extern "C" void kernel_launch(void* const* d_in, const int* in_sizes, int n_in,
                              void* d_out, int out_size) {
    const float* x     = (const float*)d_in[0];
    const float* Wq    = (const float*)d_in[1];
    const float* bq    = (const float*)d_in[2];
    const float* Wk    = (const float*)d_in[3];
    const float* bk    = (const float*)d_in[4];
    const float* Wv    = (const float*)d_in[5];
    const float* bv    = (const float*)d_in[6];
    const float* gamma = (const float*)d_in[7];
    float* out = (float*)d_out;

    pack_w_kernel<<<(NR * NC + 255) / 256, 256>>>(Wq, bq, Wk, bk, Wv, bv);

    dim3 g1(NNP / 64, NR / 64, NB);
    qkv_gemm_kernel<<<g1, 256>>>(x);

    dim3 g2(NNP / 128, NNP / 128, NB);
    energy_gemm_kernel<<<g2, 256>>>();

    dim3 g3(NNP, NB);
    softmax_stats_kernel<<<g3, 256>>>();

    dim3 gv(NKC, NB);
    vf_pack_kernel<<<gv, 256>>>();

    dim3 gp(NIT, NKC, NB);
    p_pack_kernel<<<gp, 256>>>();

    cudaFuncSetAttribute(out_gemm_tc_kernel, cudaFuncAttributeMaxDynamicSharedMemorySize, S_TOTAL);
    dim3 g4(NIT, NB);
    out_gemm_tc_kernel<<<g4, 256, S_TOTAL>>>(x, gamma, out);
}